// round 7
// baseline (speedup 1.0000x reference)
#include <cuda_runtime.h>
#include <cuda_bf16.h>

#define NL 51        // NUM_LABELS
#define LS 53        // LABEL_SIZE
#define LPAD 56      // padded to multiple of 4
#define START_IDX 51
#define END_IDX 52

__device__ __forceinline__ void grp_bar(int g) {
    // named barrier per sequence-group: warps {0,1} -> bar 1, warps {2,3} -> bar 2
    asm volatile("bar.sync %0, 64;" :: "r"(g + 1) : "memory");
}

__global__ __launch_bounds__(128, 1)
void crf_fwd_kernel(const float* __restrict__ logits,
                    const int*   __restrict__ labels,
                    const int*   __restrict__ lens,
                    const float* __restrict__ transition,
                    float* __restrict__ out, int S, int B)
{
    __shared__ float sh_T[LS * LS];
    __shared__ __align__(16) float sh_e[2][2][LPAD];   // [group][buf][state]
    __shared__ float sh_C[2][2];                       // [group][buf]
    __shared__ float sh_a[2][64];
    __shared__ float sh_red[2][64];

    const int tid = threadIdx.x;
    const int g   = tid >> 6;          // sequence group 0/1 (warps 0,1 | 2,3)
    const int j   = tid & 63;          // state index within group
    const int b   = blockIdx.x * 2 + g;
    const bool live = (b < B);
    const int len = live ? lens[b] : 1;

    // ---- transition into shared (cooperative, all 128 threads) ----
    for (int k = tid; k < LS * LS; k += 128) sh_T[k] = transition[k];
    __syncthreads();

    // ---- per-thread row of E = exp(T[j,:] - rowmax), kept in registers ----
    float Er[LPAD];
    float rmax = 0.f;
    if (j < LS) {
        rmax = -1e30f;
        #pragma unroll
        for (int i = 0; i < LS; i++) rmax = fmaxf(rmax, sh_T[j * LS + i]);
        #pragma unroll
        for (int i = 0; i < LS; i++) Er[i] = __expf(sh_T[j * LS + i] - rmax);
        #pragma unroll
        for (int i = LS; i < LPAD; i++) Er[i] = 0.f;
    } else {
        rmax = 0.f;
        #pragma unroll
        for (int i = 0; i < LPAD; i++) Er[i] = 0.f;
    }

    // ---- gold score partials (unary + binary), parallel over t within group ----
    const float* Lb  = logits + (size_t)b * S * NL;
    const int*   lab = labels + (size_t)b * S;
    if (live) {
        float gg = 0.f;
        for (int t = j; t < len; t += 64) {
            int lt = lab[t];
            gg += Lb[(size_t)t * NL + lt];
            int lp = (t == 0) ? START_IDX : lab[t - 1];
            gg += sh_T[lt * LS + lp];
        }
        if (j == 0) gg += sh_T[END_IDX * LS + lab[len - 1]];
        sh_red[g][j] = gg;
    }
    // (sh_red read only after the scan's group barriers)

    // ---- exp-domain forward recurrence ----
    // Invariant: u_j = exp(alpha_j - C); thread START broadcasts alpha_START
    // (== exact running lse of alpha, since T[START,:] == +100 and
    // logits_p[START] == -100) as the next offset. Offset 2 steps stale;
    // drift << 87 so all exps stay in range.
    float a0 = (j < LS) ? ((j == START_IDX) ? 0.f : -100.f) : -1e30f;
    float u  = __expf(a0);
    if (j < LPAD) sh_e[g][0][j] = u;
    if (j == 0) sh_C[g][0] = 0.f;      // alpha_START = 0
    float C = 0.f;

    // distance-3 prefetch of lgr = logit + rmax (lanes >= NL: -100 padding)
    float lgr0, lgr1, lgr2;
    if (live) {
        int t1 = (1 < S) ? 1 : 0;
        int t2 = (2 < S) ? 2 : S - 1;
        lgr0 = ((j < NL) ? Lb[j] : -100.f) + rmax;
        lgr1 = ((j < NL) ? Lb[(size_t)t1 * NL + j] : -100.f) + rmax;
        lgr2 = ((j < NL) ? Lb[(size_t)t2 * NL + j] : -100.f) + rmax;
    } else {
        lgr0 = lgr1 = lgr2 = -100.f;
    }

    int buf = 0;
    for (int t = 0; t < len; t++) {
        grp_bar(g);                    // publishes sh_e[g][buf], sh_C[g][buf]

        float newC = sh_C[g][buf];
        float f = __expf(lgr0 + (C - newC));   // issued early; overlaps the dot

        // rotate prefetch, fetch t+3 (clamped)
        lgr0 = lgr1; lgr1 = lgr2;
        if (live) {
            int tt = t + 3; if (tt > S - 1) tt = S - 1;
            lgr2 = ((j < NL) ? Lb[(size_t)tt * NL + j] : -100.f) + rmax;
        }

        // dot over i: 14 x float4 broadcast loads, 4 independent accumulators
        float s0 = 0.f, s1 = 0.f, s2 = 0.f, s3 = 0.f;
        const float4* p = (const float4*)sh_e[g][buf];
        #pragma unroll
        for (int q = 0; q < LPAD / 4; q++) {
            float4 v = p[q];
            s0 += v.x * Er[4 * q + 0];
            s1 += v.y * Er[4 * q + 1];
            s2 += v.z * Er[4 * q + 2];
            s3 += v.w * Er[4 * q + 3];
        }
        float s = (s0 + s1) + (s2 + s3);

        u = s * f;                      // u' = exp(alpha' - newC)
        int nb = buf ^ 1;
        if (j < LPAD) sh_e[g][nb][j] = u;
        if (j == START_IDX) sh_C[g][nb] = C + __logf(s);  // alpha'_START (exact lse)
        C = newC;
        buf = nb;
    }

    // ---- norm = lse_j(alpha_j + T[END, j]); combine with gold and write ----
    sh_a[g][j] = (j < LS) ? (C + __logf(u) + sh_T[END_IDX * LS + j]) : -1e30f;
    grp_bar(g);
    if (j == 0 && live) {
        float m = -1e30f;
        #pragma unroll
        for (int i = 0; i < LS; i++) m = fmaxf(m, sh_a[g][i]);
        float ssum = 0.f;
        #pragma unroll
        for (int i = 0; i < LS; i++) ssum += __expf(sh_a[g][i] - m);
        float norm = m + __logf(ssum);

        float gold = 0.f;
        #pragma unroll
        for (int i = 0; i < 64; i++) gold += sh_red[g][i];

        out[b] = gold - norm;
    }
}

extern "C" void kernel_launch(void* const* d_in, const int* in_sizes, int n_in,
                              void* d_out, int out_size)
{
    const float* logits     = (const float*)d_in[0];
    const int*   labels     = (const int*)  d_in[1];
    const int*   lens       = (const int*)  d_in[2];
    const float* transition = (const float*)d_in[3];
    float* out = (float*)d_out;

    int B = out_size;                 // 256
    int S = in_sizes[1] / B;          // labels is (B, S) -> 2048

    int grid = (B + 1) / 2;           // two sequences per block
    crf_fwd_kernel<<<grid, 128>>>(logits, labels, lens, transition, out, S, B);
}